// round 12
// baseline (speedup 1.0000x reference)
#include <cuda_runtime.h>
#include <cuda_bf16.h>

// dense_image_warp: out[b,y,x,c] = bilinear(image, (y,x) - flow[b,y,x])
// B=8, H=256, W=256, C=64 (fp32).
// R8 structure (one thread = 4 channels at one (y,x), loop over 8 batches,
// flow prefetched ahead) + L2 prefetch pipeline: iteration it+1's corner
// addresses are prefetched into L2 (prefetch.global.L2 — no register cost,
// cannot be re-scheduled away by ptxas) while iteration it's gathers are in
// flight, keeping DRAM misses outstanding through the compute/store phase.

__device__ __forceinline__ void stcs4(float4* p, float4 v) {
    asm volatile("st.global.cs.v4.f32 [%0], {%1,%2,%3,%4};"
                 :: "l"(p), "f"(v.x), "f"(v.y), "f"(v.z), "f"(v.w) : "memory");
}

__device__ __forceinline__ void pf_l2(const float4* p) {
    asm volatile("prefetch.global.L2 [%0];" :: "l"(p));
}

__device__ __forceinline__ float4 lerp2d(float4 tl, float4 tr, float4 bl, float4 br,
                                         float ax, float ay) {
    float4 r;
    float top, bot;
    top = fmaf(ax, tr.x - tl.x, tl.x);
    bot = fmaf(ax, br.x - bl.x, bl.x);
    r.x = fmaf(ay, bot - top, top);
    top = fmaf(ax, tr.y - tl.y, tl.y);
    bot = fmaf(ax, br.y - bl.y, bl.y);
    r.y = fmaf(ay, bot - top, top);
    top = fmaf(ax, tr.z - tl.z, tl.z);
    bot = fmaf(ax, br.z - bl.z, bl.z);
    r.z = fmaf(ay, bot - top, top);
    top = fmaf(ax, tr.w - tl.w, tl.w);
    bot = fmaf(ax, br.w - bl.w, bl.w);
    r.w = fmaf(ay, bot - top, top);
    return r;
}

// Image base (float4 units) + weights for query (y,x)-f in batch b.
__device__ __forceinline__ int mkbase(int b, int y, int x, int c4, float2 f,
                                      float& ax, float& ay) {
    const float qy = (float)y - f.x;
    const float qx = (float)x - f.y;
    const float fy = fminf(fmaxf(floorf(qy), 0.0f), 254.0f);
    const float fx = fminf(fmaxf(floorf(qx), 0.0f), 254.0f);
    ay = fminf(fmaxf(qy - fy, 0.0f), 1.0f);
    ax = fminf(fmaxf(qx - fx, 0.0f), 1.0f);
    return ((((b << 8) + (int)fy) << 8) + (int)fx) * 16 + c4;
}

__global__ __launch_bounds__(256) void warp_kernel(
    const float4* __restrict__ img,    // [B,H,W,C] as float4, pixel stride 16
    const float2* __restrict__ flow,   // [B,H,W,2] as float2, one per pixel
    float4* __restrict__ out)
{
    const int tid = blockIdx.x * blockDim.x + threadIdx.x;  // 0..2^20-1
    const int c4 = tid & 15;          // channel group 0..15
    const int p  = tid >> 4;          // (y,x) pixel index 0..65535
    const int x  = p & 255;
    const int y  = p >> 8;

    // Prologue: flow + bases for iteration 0 (batches 0, 4); flow for it 1.
    float2 f0 = __ldg(&flow[p]);
    float2 f1 = __ldg(&flow[p + 4 * 65536]);
    float axc0, ayc0, axc1, ayc1;
    int bc0 = mkbase(0, y, x, c4, f0, axc0, ayc0);
    int bc1 = mkbase(4, y, x, c4, f1, axc1, ayc1);
    f0 = __ldg(&flow[p + 1 * 65536]);
    f1 = __ldg(&flow[p + 5 * 65536]);

    #pragma unroll
    for (int it = 0; it < 4; ++it) {
        // 8 independent fully-coalesced 128-bit gathers (current iteration).
        const float4 tl0 = __ldg(img + bc0);
        const float4 tr0 = __ldg(img + bc0 + 16);
        const float4 bl0 = __ldg(img + bc0 + 16 * 256);
        const float4 br0 = __ldg(img + bc0 + 16 * 256 + 16);
        const float4 tl1 = __ldg(img + bc1);
        const float4 tr1 = __ldg(img + bc1 + 16);
        const float4 bl1 = __ldg(img + bc1 + 16 * 256);
        const float4 br1 = __ldg(img + bc1 + 16 * 256 + 16);

        int bn0 = 0, bn1 = 0;
        float axn0 = 0.f, ayn0 = 0.f, axn1 = 0.f, ayn1 = 0.f;
        if (it < 3) {
            // Compute next iteration's bases and prefetch its lines into L2.
            bn0 = mkbase(it + 1, y, x, c4, f0, axn0, ayn0);
            bn1 = mkbase(it + 5, y, x, c4, f1, axn1, ayn1);
            pf_l2(img + bn0);
            pf_l2(img + bn0 + 16);
            pf_l2(img + bn0 + 16 * 256);
            pf_l2(img + bn0 + 16 * 256 + 16);
            pf_l2(img + bn1);
            pf_l2(img + bn1 + 16);
            pf_l2(img + bn1 + 16 * 256);
            pf_l2(img + bn1 + 16 * 256 + 16);
            if (it < 2) {
                f0 = __ldg(&flow[p + (it + 2) * 65536]);
                f1 = __ldg(&flow[p + (it + 6) * 65536]);
            }
        }

        const float4 r0 = lerp2d(tl0, tr0, bl0, br0, axc0, ayc0);
        const float4 r1 = lerp2d(tl1, tr1, bl1, br1, axc1, ayc1);

        stcs4(out + tid + it * 1048576, r0);
        stcs4(out + tid + (it + 4) * 1048576, r1);

        bc0 = bn0; bc1 = bn1;
        axc0 = axn0; ayc0 = ayn0;
        axc1 = axn1; ayc1 = ayn1;
    }
}

extern "C" void kernel_launch(void* const* d_in, const int* in_sizes, int n_in,
                              void* d_out, int out_size)
{
    const float4* img  = (const float4*)d_in[0];
    const float2* flow = (const float2*)d_in[1];
    float4* out = (float4*)d_out;

    // 65536 (y,x) pixels * 16 channel-groups = 1048576 threads, 8 pixels each
    const int threads = 1 << 20;
    const int block = 256;
    const int grid = threads / block;  // 4096
    warp_kernel<<<grid, block>>>(img, flow, out);
}

// round 13
// speedup vs baseline: 1.0704x; 1.0704x over previous
#include <cuda_runtime.h>
#include <cuda_bf16.h>

// dense_image_warp: out[b,y,x,c] = bilinear(image, (y,x) - flow[b,y,x])
// B=8, H=256, W=256, C=64 (fp32).
// One thread per 8 contiguous channels (32B) at one (y,x), looping over the
// 8 batches (flow prefetched one batch ahead). All gathers/stores use native
// sm_103a 256-bit accesses (ld/st .v8.b32): 32B per lane, contiguous across
// the 8-lane pixel group -> fully coalesced with half the instructions and
// half the L1tex wavefront-queue entries of the float4 version.

struct F8 { float v[8]; };

__device__ __forceinline__ F8 ldg256(const float* p) {
    F8 r;
    asm("ld.global.nc.v8.b32 {%0,%1,%2,%3,%4,%5,%6,%7}, [%8];"
        : "=f"(r.v[0]), "=f"(r.v[1]), "=f"(r.v[2]), "=f"(r.v[3]),
          "=f"(r.v[4]), "=f"(r.v[5]), "=f"(r.v[6]), "=f"(r.v[7])
        : "l"(p));
    return r;
}

__device__ __forceinline__ void stcs256(float* p, const F8& r) {
    asm volatile("st.global.cs.v8.b32 [%0], {%1,%2,%3,%4,%5,%6,%7,%8};"
                 :: "l"(p),
                    "f"(r.v[0]), "f"(r.v[1]), "f"(r.v[2]), "f"(r.v[3]),
                    "f"(r.v[4]), "f"(r.v[5]), "f"(r.v[6]), "f"(r.v[7])
                 : "memory");
}

__global__ __launch_bounds__(256) void warp_kernel(
    const float* __restrict__ img,     // [B,H,W,C] fp32
    const float2* __restrict__ flow,   // [B,H,W,2] as float2, one per pixel
    float* __restrict__ out)
{
    const int tid = blockIdx.x * blockDim.x + threadIdx.x;  // 0..524287
    const int c8 = tid & 7;           // channel octet 0..7
    const int p  = tid >> 3;          // (y,x) pixel index 0..65535
    const int x  = p & 255;
    const int y  = p >> 8;

    // Prologue: flow for batch 0
    float2 f = __ldg(&flow[p]);

    #pragma unroll
    for (int b = 0; b < 8; ++b) {
        const float qy = (float)y - f.x;
        const float qx = (float)x - f.y;
        const float fy = fminf(fmaxf(floorf(qy), 0.0f), 254.0f);
        const float fx = fminf(fmaxf(floorf(qx), 0.0f), 254.0f);
        const float ay = fminf(fmaxf(qy - fy, 0.0f), 1.0f);
        const float ax = fminf(fmaxf(qx - fx, 0.0f), 1.0f);

        // base in floats: ((b*65536 + iy*256 + ix) * 64) + c8*8  (32B aligned)
        const int base = ((((b << 8) + (int)fy) << 8) + (int)fx) * 64 + (c8 << 3);

        // 4 independent fully-coalesced 256-bit gathers
        const F8 tl = ldg256(img + base);
        const F8 tr = ldg256(img + base + 64);            // x+1
        const F8 bl = ldg256(img + base + 16384);         // y+1
        const F8 br = ldg256(img + base + 16384 + 64);

        // Prefetch next batch's flow while gathers are in flight
        if (b < 7) f = __ldg(&flow[p + (b + 1) * 65536]);

        F8 r;
        #pragma unroll
        for (int i = 0; i < 8; ++i) {
            const float top = fmaf(ax, tr.v[i] - tl.v[i], tl.v[i]);
            const float bot = fmaf(ax, br.v[i] - bl.v[i], bl.v[i]);
            r.v[i] = fmaf(ay, bot - top, top);
        }

        // out offset (floats): (b*65536 + p)*64 + c8*8 = b*4194304 + tid*8
        stcs256(out + b * 4194304 + tid * 8, r);
    }
}

extern "C" void kernel_launch(void* const* d_in, const int* in_sizes, int n_in,
                              void* d_out, int out_size)
{
    const float*  img  = (const float*)d_in[0];
    const float2* flow = (const float2*)d_in[1];
    float* out = (float*)d_out;

    // 65536 (y,x) pixels * 8 channel-octets = 524288 threads, 8 batches each
    const int threads = 1 << 19;
    const int block = 256;
    const int grid = threads / block;  // 2048
    warp_kernel<<<grid, block>>>(img, flow, out);
}

// round 15
// speedup vs baseline: 1.2482x; 1.1661x over previous
#include <cuda_runtime.h>
#include <cuda_bf16.h>
#include <cstdint>

// dense_image_warp: out[b,y,x,c] = bilinear(image, (y,x) - flow[b,y,x])
// B=8, H=256, W=256, C=64 (fp32).
// R8 structure (one thread = 4 channels at one (y,x), loop over 8 batches,
// flow prefetch, 32 regs / 64-warp occupancy) + PARTIAL L2 residency:
// image loads use createpolicy.fractional.L2::evict_last with fraction=0.75
// (protect ~96MB of the 128MB image -> leaves victim ways for the write
// stream; fraction=1.0 self-defeats because every set fills with protected
// lines and stores must evict them anyway). Output stores stay .cs.

__device__ __forceinline__ void stcs4(float4* p, float4 v) {
    asm volatile("st.global.cs.v4.f32 [%0], {%1,%2,%3,%4};"
                 :: "l"(p), "f"(v.x), "f"(v.y), "f"(v.z), "f"(v.w) : "memory");
}

// Non-coherent load with (fractional) L2 evict_last cache-hint policy.
__device__ __forceinline__ float4 ldg_el(const float4* p, uint64_t pol) {
    float4 v;
    asm("ld.global.nc.L2::cache_hint.v4.f32 {%0,%1,%2,%3}, [%4], %5;"
        : "=f"(v.x), "=f"(v.y), "=f"(v.z), "=f"(v.w) : "l"(p), "l"(pol));
    return v;
}

__device__ __forceinline__ float4 lerp2d(float4 tl, float4 tr, float4 bl, float4 br,
                                         float ax, float ay) {
    float4 r;
    float top, bot;
    top = fmaf(ax, tr.x - tl.x, tl.x);
    bot = fmaf(ax, br.x - bl.x, bl.x);
    r.x = fmaf(ay, bot - top, top);
    top = fmaf(ax, tr.y - tl.y, tl.y);
    bot = fmaf(ax, br.y - bl.y, bl.y);
    r.y = fmaf(ay, bot - top, top);
    top = fmaf(ax, tr.z - tl.z, tl.z);
    bot = fmaf(ax, br.z - bl.z, bl.z);
    r.z = fmaf(ay, bot - top, top);
    top = fmaf(ax, tr.w - tl.w, tl.w);
    bot = fmaf(ax, br.w - bl.w, bl.w);
    r.w = fmaf(ay, bot - top, top);
    return r;
}

// Image base (float4 units) + weights for query (y,x)-f in batch b.
__device__ __forceinline__ int mkbase(int b, int y, int x, int c4, float2 f,
                                      float& ax, float& ay) {
    const float qy = (float)y - f.x;
    const float qx = (float)x - f.y;
    const float fy = fminf(fmaxf(floorf(qy), 0.0f), 254.0f);
    const float fx = fminf(fmaxf(floorf(qx), 0.0f), 254.0f);
    ay = fminf(fmaxf(qy - fy, 0.0f), 1.0f);
    ax = fminf(fmaxf(qx - fx, 0.0f), 1.0f);
    return ((((b << 8) + (int)fy) << 8) + (int)fx) * 16 + c4;
}

__global__ __launch_bounds__(256, 8) void warp_kernel(
    const float4* __restrict__ img,    // [B,H,W,C] as float4, pixel stride 16
    const float2* __restrict__ flow,   // [B,H,W,2] as float2, one per pixel
    float4* __restrict__ out)
{
    const int tid = blockIdx.x * blockDim.x + threadIdx.x;  // 0..2^20-1
    const int c4 = tid & 15;          // channel group 0..15
    const int p  = tid >> 4;          // (y,x) pixel index 0..65535
    const int x  = p & 255;
    const int y  = p >> 8;

    // Protect 75% of image lines in L2 (evict_last); the remaining 25% of
    // ways stay available as victims for the streaming writes.
    uint64_t pol;
    asm("createpolicy.fractional.L2::evict_last.b64 %0, 0.75;" : "=l"(pol));

    // Prologue: flow for batches 0 and 4
    float2 f0 = __ldg(&flow[p]);
    float2 f1 = __ldg(&flow[p + 4 * 65536]);

    #pragma unroll
    for (int it = 0; it < 4; ++it) {
        // This iteration handles batches it and it+4.
        float ax0, ay0, ax1, ay1;
        const int base0 = mkbase(it,     y, x, c4, f0, ax0, ay0);
        const int base1 = mkbase(it + 4, y, x, c4, f1, ax1, ay1);

        // 8 independent fully-coalesced 128-bit gathers, 75% L2-sticky
        const float4 tl0 = ldg_el(img + base0, pol);
        const float4 tr0 = ldg_el(img + base0 + 16, pol);
        const float4 bl0 = ldg_el(img + base0 + 16 * 256, pol);
        const float4 br0 = ldg_el(img + base0 + 16 * 256 + 16, pol);
        const float4 tl1 = ldg_el(img + base1, pol);
        const float4 tr1 = ldg_el(img + base1 + 16, pol);
        const float4 bl1 = ldg_el(img + base1 + 16 * 256, pol);
        const float4 br1 = ldg_el(img + base1 + 16 * 256 + 16, pol);

        // Prefetch next iteration's flow while gathers are in flight
        if (it < 3) {
            f0 = __ldg(&flow[p + (it + 1) * 65536]);
            f1 = __ldg(&flow[p + (it + 5) * 65536]);
        }

        const float4 r0 = lerp2d(tl0, tr0, bl0, br0, ax0, ay0);
        const float4 r1 = lerp2d(tl1, tr1, bl1, br1, ax1, ay1);

        // out offset (float4): (b*65536 + p)*16 + c4 = tid + b*1048576
        stcs4(out + tid + it * 1048576, r0);
        stcs4(out + tid + (it + 4) * 1048576, r1);
    }
}

extern "C" void kernel_launch(void* const* d_in, const int* in_sizes, int n_in,
                              void* d_out, int out_size)
{
    const float4* img  = (const float4*)d_in[0];
    const float2* flow = (const float2*)d_in[1];
    float4* out = (float4*)d_out;

    // 65536 (y,x) pixels * 16 channel-groups = 1048576 threads, 8 pixels each
    const int threads = 1 << 20;
    const int block = 256;
    const int grid = threads / block;  // 4096
    warp_kernel<<<grid, block>>>(img, flow, out);
}